// round 5
// baseline (speedup 1.0000x reference)
#include <cuda_runtime.h>
#include <cstdint>

// ChebyshevEncoder: x [B=16, N=65536, D=2] fp32 -> out [B, N, D*ORDER] fp32
// out[p*60 + d*30 + m] = T_m(x[p][d]) for pair p = b*N+n.
//
// R5: ZERO staging. One thread per output float4 (perfectly coalesced
// STG.128), recurrence recomputed per element with predicated capture.
// Since 60 % 4 == 0, each float4 lies within a single pair -> one float2
// LDG per thread (L1-broadcast across the ~15 threads sharing the pair).
// Removes STS + TMA-smem-read from L1tex entirely; DRAM becomes the only
// significant pipe.

#define ORDER 30
#define TPB   256

// T_m(x) for runtime m in [0, ORDER): full unrolled recurrence with
// predicated capture (compiles to FFMA + ISETP/SEL, no dynamic indexing).
__device__ __forceinline__ float cheb_at(float x, int m)
{
    float r   = (m == 0) ? 1.0f : x;
    float tm1 = 1.0f;
    float tc  = x;
    const float x2 = x + x;
#pragma unroll
    for (int n = 2; n < ORDER; n++) {
        const float tn = fmaf(x2, tc, -tm1);
        if (n == m) r = tn;
        tm1 = tc;
        tc  = tn;
    }
    return r;
}

__global__ __launch_bounds__(TPB) void cheb_kernel(
    const float2* __restrict__ x,
    float4* __restrict__ out,
    int total4)                      // npairs * 15
{
    const int g = blockIdx.x * TPB + threadIdx.x;
    if (g >= total4) return;

    const unsigned f = 4u * (unsigned)g;     // float offset in output
    const unsigned p = f / 60u;              // pair index
    const unsigned k = f - p * 60u;          // offset within pair, multiple of 4

    const float2 xv = __ldg(&x[p]);

    float v[4];
#pragma unroll
    for (int j = 0; j < 4; j++) {
        const unsigned kk = k + j;           // < 60
        const bool hi = (kk >= ORDER);       // d = 1 component?
        const float xx = hi ? xv.y : xv.x;
        const int  m   = hi ? (int)kk - ORDER : (int)kk;
        v[j] = cheb_at(xx, m);
    }

    out[g] = make_float4(v[0], v[1], v[2], v[3]);
}

extern "C" void kernel_launch(void* const* d_in, const int* in_sizes, int n_in,
                              void* d_out, int out_size)
{
    (void)n_in; (void)out_size;
    const float2* x = (const float2*)d_in[0];
    float4* out = (float4*)d_out;

    const int nelem  = in_sizes[0];       // B*N*D floats
    const int npairs = nelem / 2;         // B*N pairs (D=2)
    const int total4 = npairs * 15;       // output float4 count
    const int blocks = (total4 + TPB - 1) / TPB;

    cheb_kernel<<<blocks, TPB>>>(x, out, total4);
}

// round 7
// speedup vs baseline: 3.4557x; 3.4557x over previous
#include <cuda_runtime.h>
#include <cstdint>

// ChebyshevEncoder: x [B=16, N=65536, D=2] fp32 -> out [B, N, D*ORDER] fp32
// out[p*60 + d*30 + m] = T_m(x[p][d]) for pair p = b*N+n.
//
// R7 = R6 resubmitted verbatim (previous bench was an infra failure).
// R2 structure (block-staged smem -> one cp.async.bulk per CTA) with the
// exit wait relaxed to wait_group.READ: CTA retires as soon as the bulk
// engine has read smem; global writes drain after exit.

#define ORDER 30
#define TPB   128
#define BYTES_PER_PAIR 240                   // 60 floats

__device__ __forceinline__ uint32_t smem_u32(const void* p) {
    uint32_t a;
    asm("{ .reg .u64 t; cvta.to.shared.u64 t, %1; cvt.u32.u64 %0, t; }"
        : "=r"(a) : "l"(p));
    return a;
}

__global__ __launch_bounds__(TPB) void cheb_kernel(
    const float2* __restrict__ x,
    float* __restrict__ out,
    int npairs)
{
    __shared__ __align__(16) float s[TPB * 60];   // 30720 B, exact output order

    const int t = threadIdx.x;
    const int blockPair = blockIdx.x * TPB;
    const int p = blockPair + t;

    if (p < npairs) {
        const float2 xv = __ldg(&x[p]);

        float T[60];
        // d = 0 -> T[0..29]
        {
            const float xx = xv.x;
            const float x2 = xx + xx;
            T[0] = 1.0f;
            T[1] = xx;
#pragma unroll
            for (int m = 2; m < ORDER; m++)
                T[m] = fmaf(x2, T[m - 1], -T[m - 2]);
        }
        // d = 1 -> T[30..59]
        {
            const float xx = xv.y;
            const float x2 = xx + xx;
            T[ORDER + 0] = 1.0f;
            T[ORDER + 1] = xx;
#pragma unroll
            for (int m = 2; m < ORDER; m++)
                T[ORDER + m] = fmaf(x2, T[ORDER + m - 1], -T[ORDER + m - 2]);
        }

        // 15 STS.128 at 16B-unit addr 15*t + k: conflict-free within each
        // quarter-warp (15t mod 8 bijective over 8 consecutive lanes).
        float4* dst = reinterpret_cast<float4*>(&s[t * 60]);
        const float4* src = reinterpret_cast<const float4*>(T);
#pragma unroll
        for (int k = 0; k < 15; k++)
            dst[k] = src[k];
    }
    __syncthreads();

    if (t == 0) {
        int cnt = npairs - blockPair;
        if (cnt > TPB) cnt = TPB;
        if (cnt > 0) {
            const uint32_t sbytes = (uint32_t)cnt * BYTES_PER_PAIR;
            const uint32_t saddr  = smem_u32(s);
            float* gdst = out + (size_t)blockPair * 60;

            // Order generic-proxy STS before the async-proxy smem read.
            asm volatile("fence.proxy.async.shared::cta;" ::: "memory");
            asm volatile(
                "cp.async.bulk.global.shared::cta.bulk_group [%0], [%1], %2;"
                :: "l"(gdst), "r"(saddr), "r"(sbytes)
                : "memory");
            asm volatile("cp.async.bulk.commit_group;" ::: "memory");
            // Exit-safe once smem has been READ; writes drain after exit.
            asm volatile("cp.async.bulk.wait_group.read 0;" ::: "memory");
        }
    }
}

extern "C" void kernel_launch(void* const* d_in, const int* in_sizes, int n_in,
                              void* d_out, int out_size)
{
    (void)n_in; (void)out_size;
    const float2* x = (const float2*)d_in[0];
    float* out = (float*)d_out;

    const int nelem  = in_sizes[0];      // B*N*D floats
    const int npairs = nelem / 2;        // B*N pairs (D=2)
    const int blocks = (npairs + TPB - 1) / TPB;

    cheb_kernel<<<blocks, TPB>>>(x, out, npairs);
}